// round 8
// baseline (speedup 1.0000x reference)
#include <cuda_runtime.h>
#include <cuda_bf16.h>
#include <cstdint>

#define N_NODES 100000
#define MAX_EDGES 1600000
#define DIM 128

// -------- scratch (device globals only; no allocation allowed) ----------
__device__ float g_xlin[(size_t)N_NODES * DIM];  // y = dinv * (x @ W^T)  (pre-scaled)
__device__ int   g_cnt [N_NODES];                // incoming edge count (no self loop)
__device__ int   g_off [N_NODES + 1];            // CSR row offsets
__device__ int   g_cur [N_NODES];                // fill cursors
__device__ float g_dinv[N_NODES];                // rsqrt(cnt+1)
__device__ int   g_csr [MAX_EDGES];              // src node per CSR slot
__device__ int   g_bsum[128];                    // per-block scan sums
__device__ int   g_boff[128];                    // exclusive block offsets
__device__ int   g_is64;                         // edge_index layout flag

#define SCAN_B 1024
#define N_SCAN_BLOCKS ((N_NODES + SCAN_B - 1) / SCAN_B)   // 98

// ---------------- detect int64 vs int32 layout + zero counts -------------
__global__ void detect_zero_kernel(const int* __restrict__ eiw) {
    int i = blockIdx.x * blockDim.x + threadIdx.x;
    if (i < N_NODES) g_cnt[i] = 0;
    if (blockIdx.x == 0 && threadIdx.x < 32) {
        // int64 little-endian values in [0,1e5): every odd 32-bit word == 0
        int nz = 0;
        for (int k = threadIdx.x; k < 128; k += 32)
            nz |= (eiw[2 * k + 1] != 0);
        unsigned m = __ballot_sync(0xFFFFFFFFu, nz);
        if (threadIdx.x == 0) g_is64 = m ? 0 : 1;
    }
}

// ---------------- count incoming edges per dst (reads ei directly) -------
__global__ void cnt_kernel(const int* __restrict__ eiw, int E) {
    int e = blockIdx.x * blockDim.x + threadIdx.x;
    if (e >= E) return;
    int d = g_is64 ? eiw[2 * (E + e)] : eiw[E + e];
    d = min(max(d, 0), N_NODES - 1);
    atomicAdd(&g_cnt[d], 1);
}

// ---------------- dinv = rsqrt(cnt+1) (early, unblocks GEMM) --------------
__global__ void dinv_kernel() {
    int i = blockIdx.x * blockDim.x + threadIdx.x;
    if (i < N_NODES) g_dinv[i] = rsqrtf((float)(g_cnt[i] + 1));
}

// ---------------- scan phase 1: per-block inclusive scan ------------------
__global__ __launch_bounds__(SCAN_B) void scan1_kernel() {
    __shared__ int sh[SCAN_B];
    int t = threadIdx.x;
    int i = blockIdx.x * SCAN_B + t;
    int c = (i < N_NODES) ? g_cnt[i] : 0;
    sh[t] = c;
    __syncthreads();
#pragma unroll
    for (int o = 1; o < SCAN_B; o <<= 1) {
        int v = (t >= o) ? sh[t - o] : 0;
        __syncthreads();
        sh[t] += v;
        __syncthreads();
    }
    if (i < N_NODES) g_off[i] = sh[t] - c;     // local exclusive prefix
    if (t == SCAN_B - 1) g_bsum[blockIdx.x] = sh[t];
}

// ---------------- scan phase 2: scan the 98 block sums --------------------
__global__ void scan2_kernel(int nb) {
    __shared__ int sh[128];
    int t = threadIdx.x;
    int own = (t < nb) ? g_bsum[t] : 0;
    sh[t] = own;
    __syncthreads();
#pragma unroll
    for (int o = 1; o < 128; o <<= 1) {
        int v = (t >= o) ? sh[t - o] : 0;
        __syncthreads();
        sh[t] += v;
        __syncthreads();
    }
    if (t < nb) g_boff[t] = sh[t] - own;       // exclusive
}

// ---------------- scan phase 3: add block offsets, init cursors -----------
__global__ void scan3_kernel(int E) {
    int i = blockIdx.x * blockDim.x + threadIdx.x;
    if (i < N_NODES) {
        int o = g_off[i] + g_boff[i >> 10];
        g_off[i] = o;
        g_cur[i] = o;
    }
    if (i == 0) g_off[N_NODES] = E;
}

// ---------------- fill CSR with src indices (reads ei directly) -----------
__global__ void fill_kernel(const int* __restrict__ eiw, int E) {
    int e = blockIdx.x * blockDim.x + threadIdx.x;
    if (e >= E) return;
    int s, d;
    if (g_is64) {
        s = eiw[2 * e];
        d = eiw[2 * (E + e)];
    } else {
        s = eiw[e];
        d = eiw[E + e];
    }
    s = min(max(s, 0), N_NODES - 1);
    d = min(max(d, 0), N_NODES - 1);
    int pos = atomicAdd(&g_cur[d], 1);
    g_csr[pos] = s;
}

// ---------------- GEMM: y = dinv .* (x @ W^T)  (N x 128) ------------------
// 512 threads, 128-row tile, 4x8 microtile, k-major smem (all LDS vectorized).
#define GEMM_BM 128
#define GEMM_SMEM_BYTES (2 * DIM * DIM * (int)sizeof(float))   // 128 KB

__global__ __launch_bounds__(512) void gemm_kernel(const float* __restrict__ x,
                                                   const float* __restrict__ W,
                                                   int nrows) {
    extern __shared__ float smem[];
    float* xsT = smem;              // [k][r]  : xsT[k*128 + r]
    float* wt  = smem + DIM * DIM;  // [k][o]  : wt [k*128 + o] = W[o][k]

    int t = threadIdx.x;
    int row0 = blockIdx.x * GEMM_BM;

    // W transposed into smem (strided global reads; W is 64KB and L2-hot)
    for (int i = t; i < DIM * DIM; i += 512) {
        int k = i >> 7;
        int o = i & 127;
        wt[k * DIM + o] = W[o * DIM + k];
    }
    // x tile, transposed to k-major. Each iter: one float4 over k, 4 scalar STS
    // (lane-stride-1 in r -> conflict-free).
    for (int i = t; i < GEMM_BM * (DIM / 4); i += 512) {
        int r  = i >> 5;           // 0..127
        int k4 = i & 31;           // float4 index over k
        int gr = row0 + r;
        float4 v = (gr < nrows) ? ((const float4*)x)[(size_t)gr * 32 + k4]
                                : make_float4(0.f, 0.f, 0.f, 0.f);
        xsT[(k4 * 4 + 0) * DIM + r] = v.x;
        xsT[(k4 * 4 + 1) * DIM + r] = v.y;
        xsT[(k4 * 4 + 2) * DIM + r] = v.z;
        xsT[(k4 * 4 + 3) * DIM + r] = v.w;
    }
    __syncthreads();

    int cg = (t & 15) * 8;   // output col base (16 groups)
    int rg = (t >> 4) * 4;   // output row base (32 groups)

    float acc[4][8];
#pragma unroll
    for (int i = 0; i < 4; i++)
#pragma unroll
        for (int j = 0; j < 8; j++) acc[i][j] = 0.0f;

#pragma unroll 4
    for (int k = 0; k < DIM; k++) {
        float4 a4 = *(const float4*)&xsT[k * DIM + rg];      // broadcast within cg group
        float4 b0 = *(const float4*)&wt[k * DIM + cg];
        float4 b1 = *(const float4*)&wt[k * DIM + cg + 4];
        float a[4] = {a4.x, a4.y, a4.z, a4.w};
        float bv[8] = {b0.x, b0.y, b0.z, b0.w, b1.x, b1.y, b1.z, b1.w};
#pragma unroll
        for (int i = 0; i < 4; i++)
#pragma unroll
            for (int j = 0; j < 8; j++)
                acc[i][j] = fmaf(a[i], bv[j], acc[i][j]);
    }

#pragma unroll
    for (int i = 0; i < 4; i++) {
        int gr = row0 + rg + i;
        if (gr < nrows) {
            float sc = g_dinv[gr];            // pre-scale epilogue
            float4* o = (float4*)&g_xlin[(size_t)gr * DIM + cg];
            o[0] = make_float4(sc * acc[i][0], sc * acc[i][1], sc * acc[i][2], sc * acc[i][3]);
            o[1] = make_float4(sc * acc[i][4], sc * acc[i][5], sc * acc[i][6], sc * acc[i][7]);
        }
    }
}

// ---------------- gather + finalize: one warp per node --------------------
// out[n] = dinv[n] * ( sum_{s in in(n)} y[s] + y[n] ) + b,  y pre-scaled
__global__ __launch_bounds__(256) void gather_kernel(const float* __restrict__ b,
                                                     float* __restrict__ out) {
    int warp = (blockIdx.x * blockDim.x + threadIdx.x) >> 5;
    if (warp >= N_NODES) return;
    int lane = threadIdx.x & 31;

    const float4* y4 = (const float4*)g_xlin;

    int base = g_off[warp];
    int cnt = g_off[warp + 1] - base;

    float4 acc = make_float4(0.f, 0.f, 0.f, 0.f);

    int k = 0;
    for (; k + 8 <= cnt; k += 8) {
        int s[8];
#pragma unroll
        for (int j = 0; j < 8; j++) s[j] = __ldg(&g_csr[base + k + j]);
        float4 v[8];
#pragma unroll
        for (int j = 0; j < 8; j++) v[j] = __ldg(&y4[(size_t)s[j] * 32 + lane]);
#pragma unroll
        for (int j = 0; j < 8; j++) {
            acc.x += v[j].x;
            acc.y += v[j].y;
            acc.z += v[j].z;
            acc.w += v[j].w;
        }
    }
    for (; k < cnt; k++) {
        int s = __ldg(&g_csr[base + k]);
        float4 v = __ldg(&y4[(size_t)s * 32 + lane]);
        acc.x += v.x;
        acc.y += v.y;
        acc.z += v.z;
        acc.w += v.w;
    }

    // self loop (y already carries dinv[n])
    float4 yl = y4[(size_t)warp * 32 + lane];
    acc.x += yl.x;
    acc.y += yl.y;
    acc.z += yl.z;
    acc.w += yl.w;

    float di = g_dinv[warp];
    float4 bb = ((const float4*)b)[lane];

    float4 r;
    r.x = di * acc.x + bb.x;
    r.y = di * acc.y + bb.y;
    r.z = di * acc.z + bb.z;
    r.w = di * acc.w + bb.w;
    ((float4*)out)[(size_t)warp * 32 + lane] = r;
}

// -------------------------------------------------------------------------
extern "C" void kernel_launch(void* const* d_in, const int* in_sizes, int n_in,
                              void* d_out, int out_size) {
    const float* x   = (const float*)d_in[0];
    const int*   eiw = (const int*)d_in[1];   // raw 32-bit view; layout detected on device
    const float* W   = (const float*)d_in[2];
    const float* b   = (const float*)d_in[3];
    float*       out = (float*)d_out;

    int E = in_sizes[1] / 2;

    cudaFuncSetAttribute(gemm_kernel,
                         cudaFuncAttributeMaxDynamicSharedMemorySize,
                         GEMM_SMEM_BYTES);

    // fork/join resources (host-side only; no device memory)
    cudaStream_t s2;
    cudaStreamCreateWithFlags(&s2, cudaStreamNonBlocking);
    cudaEvent_t e1, e2;
    cudaEventCreateWithFlags(&e1, cudaEventDisableTiming);
    cudaEventCreateWithFlags(&e2, cudaEventDisableTiming);

    // serial prefix: detect -> cnt -> dinv
    detect_zero_kernel<<<(N_NODES + 255) / 256, 256>>>(eiw);
    cnt_kernel<<<(E + 255) / 256, 256>>>(eiw, E);
    dinv_kernel<<<(N_NODES + 255) / 256, 256>>>();

    // fork: GEMM (branch A) runs concurrently with CSR build (branch B)
    cudaEventRecord(e1, 0);
    cudaStreamWaitEvent(s2, e1, 0);
    gemm_kernel<<<(N_NODES + GEMM_BM - 1) / GEMM_BM, 512, GEMM_SMEM_BYTES, s2>>>(x, W, N_NODES);
    cudaEventRecord(e2, s2);

    scan1_kernel<<<N_SCAN_BLOCKS, SCAN_B>>>();
    scan2_kernel<<<1, 128>>>(N_SCAN_BLOCKS);
    scan3_kernel<<<(N_NODES + 255) / 256, 256>>>(E);
    fill_kernel<<<(E + 255) / 256, 256>>>(eiw, E);

    // join, then gather
    cudaStreamWaitEvent(0, e2, 0);
    int gather_blocks = (N_NODES * 32 + 255) / 256;
    gather_kernel<<<gather_blocks, 256>>>(b, out);

    cudaEventDestroy(e1);
    cudaEventDestroy(e2);
    cudaStreamDestroy(s2);
}

// round 14
// speedup vs baseline: 1.6668x; 1.6668x over previous
#include <cuda_runtime.h>
#include <cuda_bf16.h>
#include <cstdint>

#define N_NODES 100000
#define MAX_EDGES 1600000
#define DIM 128

// -------- scratch (device globals only; no allocation allowed) ----------
__device__ float g_xlin[(size_t)N_NODES * DIM];  // y = dinv * (x @ W^T)
__device__ int   g_cnt [N_NODES];
__device__ int   g_off [N_NODES + 1];
__device__ int   g_cur [N_NODES];
__device__ float g_dinv[N_NODES];
__device__ int   g_csr [MAX_EDGES];
__device__ int   g_bsum[128];
__device__ int   g_boff[128];
__device__ int   g_is64;
__device__ __nv_bfloat16 g_Wh[DIM * DIM];   // W split-bf16 hi, row-major [o][k]
__device__ __nv_bfloat16 g_Wl[DIM * DIM];   // W split-bf16 lo

#define SCAN_B 1024
#define N_SCAN_BLOCKS ((N_NODES + SCAN_B - 1) / SCAN_B)   // 98

// ---------------- detect int64 vs int32 layout + zero counts -------------
__global__ void detect_zero_kernel(const int* __restrict__ eiw) {
    int i = blockIdx.x * blockDim.x + threadIdx.x;
    if (i < N_NODES) g_cnt[i] = 0;
    if (blockIdx.x == 0 && threadIdx.x < 32) {
        int nz = 0;
        for (int k = threadIdx.x; k < 128; k += 32)
            nz |= (eiw[2 * k + 1] != 0);
        unsigned m = __ballot_sync(0xFFFFFFFFu, nz);
        if (threadIdx.x == 0) g_is64 = m ? 0 : 1;
    }
}

__global__ void cnt_kernel(const int* __restrict__ eiw, int E) {
    int e = blockIdx.x * blockDim.x + threadIdx.x;
    if (e >= E) return;
    int d = g_is64 ? eiw[2 * (E + e)] : eiw[E + e];
    d = min(max(d, 0), N_NODES - 1);
    atomicAdd(&g_cnt[d], 1);
}

__global__ void dinv_kernel() {
    int i = blockIdx.x * blockDim.x + threadIdx.x;
    if (i < N_NODES) g_dinv[i] = rsqrtf((float)(g_cnt[i] + 1));
}

__global__ __launch_bounds__(SCAN_B) void scan1_kernel() {
    __shared__ int sh[SCAN_B];
    int t = threadIdx.x;
    int i = blockIdx.x * SCAN_B + t;
    int c = (i < N_NODES) ? g_cnt[i] : 0;
    sh[t] = c;
    __syncthreads();
#pragma unroll
    for (int o = 1; o < SCAN_B; o <<= 1) {
        int v = (t >= o) ? sh[t - o] : 0;
        __syncthreads();
        sh[t] += v;
        __syncthreads();
    }
    if (i < N_NODES) g_off[i] = sh[t] - c;
    if (t == SCAN_B - 1) g_bsum[blockIdx.x] = sh[t];
}

__global__ void scan2_kernel(int nb) {
    __shared__ int sh[128];
    int t = threadIdx.x;
    int own = (t < nb) ? g_bsum[t] : 0;
    sh[t] = own;
    __syncthreads();
#pragma unroll
    for (int o = 1; o < 128; o <<= 1) {
        int v = (t >= o) ? sh[t - o] : 0;
        __syncthreads();
        sh[t] += v;
        __syncthreads();
    }
    if (t < nb) g_boff[t] = sh[t] - own;
}

__global__ void scan3_kernel(int E) {
    int i = blockIdx.x * blockDim.x + threadIdx.x;
    if (i < N_NODES) {
        int o = g_off[i] + g_boff[i >> 10];
        g_off[i] = o;
        g_cur[i] = o;
    }
    if (i == 0) g_off[N_NODES] = E;
}

__global__ void fill_kernel(const int* __restrict__ eiw, int E) {
    int e = blockIdx.x * blockDim.x + threadIdx.x;
    if (e >= E) return;
    int s, d;
    if (g_is64) {
        s = eiw[2 * e];
        d = eiw[2 * (E + e)];
    } else {
        s = eiw[e];
        d = eiw[E + e];
    }
    s = min(max(s, 0), N_NODES - 1);
    d = min(max(d, 0), N_NODES - 1);
    int pos = atomicAdd(&g_cur[d], 1);
    g_csr[pos] = s;
}

// ---------------- W prep: split to bf16 hi/lo ------------------------------
__global__ void wprep_kernel(const float* __restrict__ W) {
    int i = blockIdx.x * blockDim.x + threadIdx.x;
    if (i >= DIM * DIM) return;
    float w = W[i];
    __nv_bfloat16 h = __float2bfloat16_rn(w);
    __nv_bfloat16 l = __float2bfloat16_rn(w - __bfloat162float(h));
    g_Wh[i] = h;
    g_Wl[i] = l;
}

// ---------------- tensor-core GEMM via mma.sync (HMMA, sm_80+ PTX) --------
// y = dinv .* (x @ W^T), split bf16: xh*Wh^T + xh*Wl^T + xl*Wh^T, fp32 accum.
// Block: 128 rows x 128 cols, 256 threads (8 warps), warp tile 32x64.
#define APAD 136   // bf16 elements per smem row (272 B => 4-bank shift/row)
#define TILE_E (128 * APAD)
#define GEMM_TC_SMEM (4 * TILE_E * (int)sizeof(__nv_bfloat16))   // 139264 B

__device__ __forceinline__ void mma16816(float* c, const uint32_t* a, uint32_t b0, uint32_t b1) {
    asm volatile(
        "mma.sync.aligned.m16n8k16.row.col.f32.bf16.bf16.f32 "
        "{%0,%1,%2,%3}, {%4,%5,%6,%7}, {%8,%9}, {%0,%1,%2,%3};"
        : "+f"(c[0]), "+f"(c[1]), "+f"(c[2]), "+f"(c[3])
        : "r"(a[0]), "r"(a[1]), "r"(a[2]), "r"(a[3]), "r"(b0), "r"(b1));
}

__global__ __launch_bounds__(256) void gemm_tc_kernel(const float* __restrict__ x,
                                                      int nrows) {
    extern __shared__ __nv_bfloat16 smem[];
    __nv_bfloat16* Ah = smem;
    __nv_bfloat16* Al = Ah + TILE_E;
    __nv_bfloat16* Bh = Al + TILE_E;
    __nv_bfloat16* Bl = Bh + TILE_E;

    int t = threadIdx.x;
    int row0 = blockIdx.x * 128;

    // ---- W tiles: copy hi/lo images into padded smem (16B chunks) ----
    for (int i = t; i < 128 * 16; i += 256) {
        int r = i >> 4, c8 = i & 15;                 // 16 x 8-bf16 chunks per row
        uint4 vh = ((const uint4*)g_Wh)[i];
        uint4 vl = ((const uint4*)g_Wl)[i];
        *(uint4*)&Bh[r * APAD + c8 * 8] = vh;
        *(uint4*)&Bl[r * APAD + c8 * 8] = vl;
    }
    // ---- x tile: load float4, split to bf16 hi/lo ----
    for (int i = t; i < 128 * 32; i += 256) {
        int r = i >> 5, k4 = i & 31;
        int gr = row0 + r;
        float4 v = (gr < nrows) ? ((const float4*)x)[(size_t)gr * 32 + k4]
                                : make_float4(0.f, 0.f, 0.f, 0.f);
        __nv_bfloat16 h0 = __float2bfloat16_rn(v.x);
        __nv_bfloat16 h1 = __float2bfloat16_rn(v.y);
        __nv_bfloat16 h2 = __float2bfloat16_rn(v.z);
        __nv_bfloat16 h3 = __float2bfloat16_rn(v.w);
        __nv_bfloat162 hp0, hp1, lp0, lp1;
        hp0.x = h0; hp0.y = h1; hp1.x = h2; hp1.y = h3;
        lp0.x = __float2bfloat16_rn(v.x - __bfloat162float(h0));
        lp0.y = __float2bfloat16_rn(v.y - __bfloat162float(h1));
        lp1.x = __float2bfloat16_rn(v.z - __bfloat162float(h2));
        lp1.y = __float2bfloat16_rn(v.w - __bfloat162float(h3));
        uint2 hv, lv;
        hv.x = *(uint32_t*)&hp0; hv.y = *(uint32_t*)&hp1;
        lv.x = *(uint32_t*)&lp0; lv.y = *(uint32_t*)&lp1;
        *(uint2*)&Ah[r * APAD + k4 * 4] = hv;
        *(uint2*)&Al[r * APAD + k4 * 4] = lv;
    }
    __syncthreads();

    int wid = t >> 5, lane = t & 31;
    int g = lane >> 2, tg = lane & 3;
    int mrow0 = (wid >> 1) * 32;     // 4 M-warps
    int ncol0 = (wid & 1) * 64;      // 2 N-warps

    float acc[2][8][4];
#pragma unroll
    for (int mf = 0; mf < 2; mf++)
#pragma unroll
        for (int nf = 0; nf < 8; nf++)
#pragma unroll
            for (int j = 0; j < 4; j++) acc[mf][nf][j] = 0.0f;

    const __nv_bfloat16* Abuf[3] = {Ah, Ah, Al};
    const __nv_bfloat16* Bbuf[3] = {Bh, Bl, Bh};

#pragma unroll
    for (int term = 0; term < 3; term++) {
        const __nv_bfloat16* A = Abuf[term];
        const __nv_bfloat16* B = Bbuf[term];
#pragma unroll
        for (int ks = 0; ks < 8; ks++) {
            int k0 = ks * 16;
            uint32_t a[2][4];
#pragma unroll
            for (int mf = 0; mf < 2; mf++) {
                int r = mrow0 + mf * 16;
                a[mf][0] = *(const uint32_t*)&A[(r + g)     * APAD + k0 + tg * 2];
                a[mf][1] = *(const uint32_t*)&A[(r + g + 8) * APAD + k0 + tg * 2];
                a[mf][2] = *(const uint32_t*)&A[(r + g)     * APAD + k0 + tg * 2 + 8];
                a[mf][3] = *(const uint32_t*)&A[(r + g + 8) * APAD + k0 + tg * 2 + 8];
            }
#pragma unroll
            for (int nf = 0; nf < 8; nf++) {
                int n = ncol0 + nf * 8;
                uint32_t b0 = *(const uint32_t*)&B[(n + g) * APAD + k0 + tg * 2];
                uint32_t b1 = *(const uint32_t*)&B[(n + g) * APAD + k0 + tg * 2 + 8];
                mma16816(acc[0][nf], a[0], b0, b1);
                mma16816(acc[1][nf], a[1], b0, b1);
            }
        }
    }

    // ---- epilogue: scale rows by dinv, store float2 ----
#pragma unroll
    for (int mf = 0; mf < 2; mf++) {
        int r0 = row0 + mrow0 + mf * 16 + g;
        int r1 = r0 + 8;
        float d0 = (r0 < nrows) ? g_dinv[r0] : 0.0f;
        float d1 = (r1 < nrows) ? g_dinv[r1] : 0.0f;
#pragma unroll
        for (int nf = 0; nf < 8; nf++) {
            int col = ncol0 + nf * 8 + tg * 2;
            if (r0 < nrows)
                *(float2*)&g_xlin[(size_t)r0 * DIM + col] =
                    make_float2(d0 * acc[mf][nf][0], d0 * acc[mf][nf][1]);
            if (r1 < nrows)
                *(float2*)&g_xlin[(size_t)r1 * DIM + col] =
                    make_float2(d1 * acc[mf][nf][2], d1 * acc[mf][nf][3]);
        }
    }
}

// ---------------- gather + finalize: one warp per node --------------------
__global__ __launch_bounds__(256) void gather_kernel(const float* __restrict__ b,
                                                     float* __restrict__ out) {
    int warp = (blockIdx.x * blockDim.x + threadIdx.x) >> 5;
    if (warp >= N_NODES) return;
    int lane = threadIdx.x & 31;

    const float4* y4 = (const float4*)g_xlin;

    int base = g_off[warp];
    int cnt = g_off[warp + 1] - base;

    float4 acc = make_float4(0.f, 0.f, 0.f, 0.f);

    int k = 0;
    for (; k + 8 <= cnt; k += 8) {
        int s[8];
#pragma unroll
        for (int j = 0; j < 8; j++) s[j] = __ldg(&g_csr[base + k + j]);
        float4 v[8];
#pragma unroll
        for (int j = 0; j < 8; j++) v[j] = __ldg(&y4[(size_t)s[j] * 32 + lane]);
#pragma unroll
        for (int j = 0; j < 8; j++) {
            acc.x += v[j].x; acc.y += v[j].y; acc.z += v[j].z; acc.w += v[j].w;
        }
    }
    for (; k < cnt; k++) {
        int s = __ldg(&g_csr[base + k]);
        float4 v = __ldg(&y4[(size_t)s * 32 + lane]);
        acc.x += v.x; acc.y += v.y; acc.z += v.z; acc.w += v.w;
    }

    float4 yl = y4[(size_t)warp * 32 + lane];
    acc.x += yl.x; acc.y += yl.y; acc.z += yl.z; acc.w += yl.w;

    float di = g_dinv[warp];
    float4 bb = ((const float4*)b)[lane];

    float4 r;
    r.x = di * acc.x + bb.x;
    r.y = di * acc.y + bb.y;
    r.z = di * acc.z + bb.z;
    r.w = di * acc.w + bb.w;
    ((float4*)out)[(size_t)warp * 32 + lane] = r;
}

// -------------------------------------------------------------------------
extern "C" void kernel_launch(void* const* d_in, const int* in_sizes, int n_in,
                              void* d_out, int out_size) {
    const float* x   = (const float*)d_in[0];
    const int*   eiw = (const int*)d_in[1];
    const float* W   = (const float*)d_in[2];
    const float* b   = (const float*)d_in[3];
    float*       out = (float*)d_out;

    int E = in_sizes[1] / 2;

    cudaFuncSetAttribute(gemm_tc_kernel,
                         cudaFuncAttributeMaxDynamicSharedMemorySize,
                         GEMM_TC_SMEM);

    cudaStream_t s2;
    cudaStreamCreateWithFlags(&s2, cudaStreamNonBlocking);
    cudaEvent_t e1, e2;
    cudaEventCreateWithFlags(&e1, cudaEventDisableTiming);
    cudaEventCreateWithFlags(&e2, cudaEventDisableTiming);

    // branch A prep (needs only W): run first on s2
    wprep_kernel<<<(DIM * DIM + 255) / 256, 256, 0, s2>>>(W);

    // serial prefix on stream 0: detect -> cnt -> dinv
    detect_zero_kernel<<<(N_NODES + 255) / 256, 256>>>(eiw);
    cnt_kernel<<<(E + 255) / 256, 256>>>(eiw, E);
    dinv_kernel<<<(N_NODES + 255) / 256, 256>>>();

    // fork: HMMA GEMM on s2 after dinv ready
    cudaEventRecord(e1, 0);
    cudaStreamWaitEvent(s2, e1, 0);
    int gblocks = (N_NODES + 127) / 128;
    gemm_tc_kernel<<<gblocks, 256, GEMM_TC_SMEM, s2>>>(x, N_NODES);
    cudaEventRecord(e2, s2);

    // branch B: CSR build on stream 0
    scan1_kernel<<<N_SCAN_BLOCKS, SCAN_B>>>();
    scan2_kernel<<<1, 128>>>(N_SCAN_BLOCKS);
    scan3_kernel<<<(N_NODES + 255) / 256, 256>>>(E);
    fill_kernel<<<(E + 255) / 256, 256>>>(eiw, E);

    // join, then gather
    cudaStreamWaitEvent(0, e2, 0);
    int gather_blocks = (N_NODES * 32 + 255) / 256;
    gather_kernel<<<gather_blocks, 256>>>(b, out);

    cudaEventDestroy(e1);
    cudaEventDestroy(e2);
    cudaStreamDestroy(s2);
}

// round 16
// speedup vs baseline: 1.7479x; 1.0486x over previous
#include <cuda_runtime.h>
#include <cuda_bf16.h>
#include <cuda_fp16.h>
#include <cstdint>

#define N_NODES 100000
#define MAX_EDGES 1600000
#define DIM 128

// -------- scratch (device globals only; no allocation allowed) ----------
__device__ __half g_ylin[(size_t)N_NODES * DIM];  // y = dinv*(x@W^T) in fp16
__device__ int    g_cnt [N_NODES];
__device__ int    g_off [N_NODES + 1];
__device__ int    g_cur [N_NODES];
__device__ float  g_dinv[N_NODES];
__device__ int    g_csr [MAX_EDGES];
__device__ int    g_bsum[128];
__device__ int    g_boff[128];
__device__ int    g_is64;
__device__ __nv_bfloat16 g_Wh[DIM * DIM];   // W split-bf16 hi, row-major [o][k]
__device__ __nv_bfloat16 g_Wl[DIM * DIM];   // W split-bf16 lo

#define SCAN_B 1024
#define N_SCAN_BLOCKS ((N_NODES + SCAN_B - 1) / SCAN_B)   // 98

// ---------------- detect int64 vs int32 layout + zero counts -------------
__global__ void detect_zero_kernel(const int* __restrict__ eiw) {
    int i = blockIdx.x * blockDim.x + threadIdx.x;
    if (i < N_NODES) g_cnt[i] = 0;
    if (blockIdx.x == 0 && threadIdx.x < 32) {
        int nz = 0;
        for (int k = threadIdx.x; k < 128; k += 32)
            nz |= (eiw[2 * k + 1] != 0);
        unsigned m = __ballot_sync(0xFFFFFFFFu, nz);
        if (threadIdx.x == 0) g_is64 = m ? 0 : 1;
    }
}

// ---------------- count: 2 edges per thread -------------------------------
__global__ void cnt_kernel(const int* __restrict__ eiw, int E) {
    int e0 = 2 * (blockIdx.x * blockDim.x + threadIdx.x);
    if (e0 >= E) return;
    int d0, d1 = -1;
    if (g_is64) {
        // dst words at 2*(E+e): e0 even & E even -> 16B aligned
        int4 v = *(const int4*)&eiw[2 * (E + e0)];
        d0 = v.x;
        if (e0 + 1 < E) d1 = v.z;
    } else {
        int2 v = *(const int2*)&eiw[E + e0];
        d0 = v.x;
        if (e0 + 1 < E) d1 = v.y;
    }
    d0 = min(max(d0, 0), N_NODES - 1);
    atomicAdd(&g_cnt[d0], 1);
    if (d1 >= 0 || (e0 + 1 < E)) {
        if (e0 + 1 < E) {
            d1 = min(max(d1, 0), N_NODES - 1);
            atomicAdd(&g_cnt[d1], 1);
        }
    }
}

__global__ void dinv_kernel() {
    int i = blockIdx.x * blockDim.x + threadIdx.x;
    if (i < N_NODES) g_dinv[i] = rsqrtf((float)(g_cnt[i] + 1));
}

__global__ __launch_bounds__(SCAN_B) void scan1_kernel() {
    __shared__ int sh[SCAN_B];
    int t = threadIdx.x;
    int i = blockIdx.x * SCAN_B + t;
    int c = (i < N_NODES) ? g_cnt[i] : 0;
    sh[t] = c;
    __syncthreads();
#pragma unroll
    for (int o = 1; o < SCAN_B; o <<= 1) {
        int v = (t >= o) ? sh[t - o] : 0;
        __syncthreads();
        sh[t] += v;
        __syncthreads();
    }
    if (i < N_NODES) g_off[i] = sh[t] - c;
    if (t == SCAN_B - 1) g_bsum[blockIdx.x] = sh[t];
}

__global__ void scan2_kernel(int nb) {
    __shared__ int sh[128];
    int t = threadIdx.x;
    int own = (t < nb) ? g_bsum[t] : 0;
    sh[t] = own;
    __syncthreads();
#pragma unroll
    for (int o = 1; o < 128; o <<= 1) {
        int v = (t >= o) ? sh[t - o] : 0;
        __syncthreads();
        sh[t] += v;
        __syncthreads();
    }
    if (t < nb) g_boff[t] = sh[t] - own;
}

__global__ void scan3_kernel(int E) {
    int i = blockIdx.x * blockDim.x + threadIdx.x;
    if (i < N_NODES) {
        int o = g_off[i] + g_boff[i >> 10];
        g_off[i] = o;
        g_cur[i] = o;
    }
    if (i == 0) g_off[N_NODES] = E;
}

// ---------------- fill CSR: 2 edges per thread ----------------------------
__global__ void fill_kernel(const int* __restrict__ eiw, int E) {
    int e0 = 2 * (blockIdx.x * blockDim.x + threadIdx.x);
    if (e0 >= E) return;
    int s0, d0, s1 = 0, d1 = 0;
    bool two = (e0 + 1 < E);
    if (g_is64) {
        int4 sv = *(const int4*)&eiw[2 * e0];
        int4 dv = *(const int4*)&eiw[2 * (E + e0)];
        s0 = sv.x; d0 = dv.x;
        if (two) { s1 = sv.z; d1 = dv.z; }
    } else {
        int2 sv = *(const int2*)&eiw[e0];
        int2 dv = *(const int2*)&eiw[E + e0];
        s0 = sv.x; d0 = dv.x;
        if (two) { s1 = sv.y; d1 = dv.y; }
    }
    s0 = min(max(s0, 0), N_NODES - 1);
    d0 = min(max(d0, 0), N_NODES - 1);
    int p0 = atomicAdd(&g_cur[d0], 1);
    g_csr[p0] = s0;
    if (two) {
        s1 = min(max(s1, 0), N_NODES - 1);
        d1 = min(max(d1, 0), N_NODES - 1);
        int p1 = atomicAdd(&g_cur[d1], 1);
        g_csr[p1] = s1;
    }
}

// ---------------- W prep: split to bf16 hi/lo ------------------------------
__global__ void wprep_kernel(const float* __restrict__ W) {
    int i = blockIdx.x * blockDim.x + threadIdx.x;
    if (i >= DIM * DIM) return;
    float w = W[i];
    __nv_bfloat16 h = __float2bfloat16_rn(w);
    __nv_bfloat16 l = __float2bfloat16_rn(w - __bfloat162float(h));
    g_Wh[i] = h;
    g_Wl[i] = l;
}

// ---------------- tensor-core GEMM via mma.sync (HMMA) --------------------
// y = dinv .* (x @ W^T) stored fp16. Split bf16, fp32 accumulation.
#define APAD 136
#define TILE_E (128 * APAD)
#define GEMM_TC_SMEM (4 * TILE_E * (int)sizeof(__nv_bfloat16))

__device__ __forceinline__ void mma16816(float* c, const uint32_t* a, uint32_t b0, uint32_t b1) {
    asm volatile(
        "mma.sync.aligned.m16n8k16.row.col.f32.bf16.bf16.f32 "
        "{%0,%1,%2,%3}, {%4,%5,%6,%7}, {%8,%9}, {%0,%1,%2,%3};"
        : "+f"(c[0]), "+f"(c[1]), "+f"(c[2]), "+f"(c[3])
        : "r"(a[0]), "r"(a[1]), "r"(a[2]), "r"(a[3]), "r"(b0), "r"(b1));
}

__global__ __launch_bounds__(256) void gemm_tc_kernel(const float* __restrict__ x,
                                                      int nrows) {
    extern __shared__ __nv_bfloat16 smem[];
    __nv_bfloat16* Ah = smem;
    __nv_bfloat16* Al = Ah + TILE_E;
    __nv_bfloat16* Bh = Al + TILE_E;
    __nv_bfloat16* Bl = Bh + TILE_E;

    int t = threadIdx.x;
    int row0 = blockIdx.x * 128;

    for (int i = t; i < 128 * 16; i += 256) {
        int r = i >> 4, c8 = i & 15;
        uint4 vh = ((const uint4*)g_Wh)[i];
        uint4 vl = ((const uint4*)g_Wl)[i];
        *(uint4*)&Bh[r * APAD + c8 * 8] = vh;
        *(uint4*)&Bl[r * APAD + c8 * 8] = vl;
    }
    for (int i = t; i < 128 * 32; i += 256) {
        int r = i >> 5, k4 = i & 31;
        int gr = row0 + r;
        float4 v = (gr < nrows) ? ((const float4*)x)[(size_t)gr * 32 + k4]
                                : make_float4(0.f, 0.f, 0.f, 0.f);
        __nv_bfloat16 h0 = __float2bfloat16_rn(v.x);
        __nv_bfloat16 h1 = __float2bfloat16_rn(v.y);
        __nv_bfloat16 h2 = __float2bfloat16_rn(v.z);
        __nv_bfloat16 h3 = __float2bfloat16_rn(v.w);
        __nv_bfloat162 hp0, hp1, lp0, lp1;
        hp0.x = h0; hp0.y = h1; hp1.x = h2; hp1.y = h3;
        lp0.x = __float2bfloat16_rn(v.x - __bfloat162float(h0));
        lp0.y = __float2bfloat16_rn(v.y - __bfloat162float(h1));
        lp1.x = __float2bfloat16_rn(v.z - __bfloat162float(h2));
        lp1.y = __float2bfloat16_rn(v.w - __bfloat162float(h3));
        uint2 hv, lv;
        hv.x = *(uint32_t*)&hp0; hv.y = *(uint32_t*)&hp1;
        lv.x = *(uint32_t*)&lp0; lv.y = *(uint32_t*)&lp1;
        *(uint2*)&Ah[r * APAD + k4 * 4] = hv;
        *(uint2*)&Al[r * APAD + k4 * 4] = lv;
    }
    __syncthreads();

    int wid = t >> 5, lane = t & 31;
    int g = lane >> 2, tg = lane & 3;
    int mrow0 = (wid >> 1) * 32;
    int ncol0 = (wid & 1) * 64;

    float acc[2][8][4];
#pragma unroll
    for (int mf = 0; mf < 2; mf++)
#pragma unroll
        for (int nf = 0; nf < 8; nf++)
#pragma unroll
            for (int j = 0; j < 4; j++) acc[mf][nf][j] = 0.0f;

    const __nv_bfloat16* Abuf[3] = {Ah, Ah, Al};
    const __nv_bfloat16* Bbuf[3] = {Bh, Bl, Bh};

#pragma unroll
    for (int term = 0; term < 3; term++) {
        const __nv_bfloat16* A = Abuf[term];
        const __nv_bfloat16* B = Bbuf[term];
#pragma unroll
        for (int ks = 0; ks < 8; ks++) {
            int k0 = ks * 16;
            uint32_t a[2][4];
#pragma unroll
            for (int mf = 0; mf < 2; mf++) {
                int r = mrow0 + mf * 16;
                a[mf][0] = *(const uint32_t*)&A[(r + g)     * APAD + k0 + tg * 2];
                a[mf][1] = *(const uint32_t*)&A[(r + g + 8) * APAD + k0 + tg * 2];
                a[mf][2] = *(const uint32_t*)&A[(r + g)     * APAD + k0 + tg * 2 + 8];
                a[mf][3] = *(const uint32_t*)&A[(r + g + 8) * APAD + k0 + tg * 2 + 8];
            }
#pragma unroll
            for (int nf = 0; nf < 8; nf++) {
                int n = ncol0 + nf * 8;
                uint32_t b0 = *(const uint32_t*)&B[(n + g) * APAD + k0 + tg * 2];
                uint32_t b1 = *(const uint32_t*)&B[(n + g) * APAD + k0 + tg * 2 + 8];
                mma16816(acc[0][nf], a[0], b0, b1);
                mma16816(acc[1][nf], a[1], b0, b1);
            }
        }
    }

    // ---- epilogue: scale by dinv, convert to fp16, store half2 ----
#pragma unroll
    for (int mf = 0; mf < 2; mf++) {
        int r0 = row0 + mrow0 + mf * 16 + g;
        int r1 = r0 + 8;
        float d0 = (r0 < nrows) ? g_dinv[r0] : 0.0f;
        float d1 = (r1 < nrows) ? g_dinv[r1] : 0.0f;
#pragma unroll
        for (int nf = 0; nf < 8; nf++) {
            int col = ncol0 + nf * 8 + tg * 2;
            if (r0 < nrows) {
                __half2 h = __floats2half2_rn(d0 * acc[mf][nf][0], d0 * acc[mf][nf][1]);
                *(__half2*)&g_ylin[(size_t)r0 * DIM + col] = h;
            }
            if (r1 < nrows) {
                __half2 h = __floats2half2_rn(d1 * acc[mf][nf][2], d1 * acc[mf][nf][3]);
                *(__half2*)&g_ylin[(size_t)r1 * DIM + col] = h;
            }
        }
    }
}

// ---------------- gather + finalize: one warp per node --------------------
// out[n] = dinv[n] * ( sum_{s in in(n)} y[s] + y[n] ) + b, y fp16 (256B/row)
__global__ __launch_bounds__(256) void gather_kernel(const float* __restrict__ b,
                                                     float* __restrict__ out) {
    int warp = (blockIdx.x * blockDim.x + threadIdx.x) >> 5;
    if (warp >= N_NODES) return;
    int lane = threadIdx.x & 31;

    const uint2* y2 = (const uint2*)g_ylin;   // 8B = 4 halves per lane; 32 lanes = row

    int base = g_off[warp];
    int cnt = g_off[warp + 1] - base;

    float4 acc = make_float4(0.f, 0.f, 0.f, 0.f);

    int k = 0;
    for (; k + 8 <= cnt; k += 8) {
        int s[8];
#pragma unroll
        for (int j = 0; j < 8; j++) s[j] = __ldg(&g_csr[base + k + j]);
        uint2 v[8];
#pragma unroll
        for (int j = 0; j < 8; j++) v[j] = __ldg(&y2[(size_t)s[j] * 32 + lane]);
#pragma unroll
        for (int j = 0; j < 8; j++) {
            float2 f0 = __half22float2(*(__half2*)&v[j].x);
            float2 f1 = __half22float2(*(__half2*)&v[j].y);
            acc.x += f0.x; acc.y += f0.y; acc.z += f1.x; acc.w += f1.y;
        }
    }
    for (; k < cnt; k++) {
        int s = __ldg(&g_csr[base + k]);
        uint2 v = __ldg(&y2[(size_t)s * 32 + lane]);
        float2 f0 = __half22float2(*(__half2*)&v.x);
        float2 f1 = __half22float2(*(__half2*)&v.y);
        acc.x += f0.x; acc.y += f0.y; acc.z += f1.x; acc.w += f1.y;
    }

    // self loop
    {
        uint2 v = y2[(size_t)warp * 32 + lane];
        float2 f0 = __half22float2(*(__half2*)&v.x);
        float2 f1 = __half22float2(*(__half2*)&v.y);
        acc.x += f0.x; acc.y += f0.y; acc.z += f1.x; acc.w += f1.y;
    }

    float di = g_dinv[warp];
    float4 bb = ((const float4*)b)[lane];

    float4 r;
    r.x = di * acc.x + bb.x;
    r.y = di * acc.y + bb.y;
    r.z = di * acc.z + bb.z;
    r.w = di * acc.w + bb.w;
    ((float4*)out)[(size_t)warp * 32 + lane] = r;
}

// -------------------------------------------------------------------------
extern "C" void kernel_launch(void* const* d_in, const int* in_sizes, int n_in,
                              void* d_out, int out_size) {
    const float* x   = (const float*)d_in[0];
    const int*   eiw = (const int*)d_in[1];
    const float* W   = (const float*)d_in[2];
    const float* b   = (const float*)d_in[3];
    float*       out = (float*)d_out;

    int E = in_sizes[1] / 2;

    cudaFuncSetAttribute(gemm_tc_kernel,
                         cudaFuncAttributeMaxDynamicSharedMemorySize,
                         GEMM_TC_SMEM);

    cudaStream_t s2;
    cudaStreamCreateWithFlags(&s2, cudaStreamNonBlocking);
    cudaEvent_t e1, e2;
    cudaEventCreateWithFlags(&e1, cudaEventDisableTiming);
    cudaEventCreateWithFlags(&e2, cudaEventDisableTiming);

    // branch A prep (needs only W)
    wprep_kernel<<<(DIM * DIM + 255) / 256, 256, 0, s2>>>(W);

    // serial prefix: detect -> cnt -> dinv
    detect_zero_kernel<<<(N_NODES + 255) / 256, 256>>>(eiw);
    int cntThreads = (E + 1) / 2;
    cnt_kernel<<<(cntThreads + 255) / 256, 256>>>(eiw, E);
    dinv_kernel<<<(N_NODES + 255) / 256, 256>>>();

    // fork: HMMA GEMM on s2 after dinv ready
    cudaEventRecord(e1, 0);
    cudaStreamWaitEvent(s2, e1, 0);
    int gblocks = (N_NODES + 127) / 128;
    gemm_tc_kernel<<<gblocks, 256, GEMM_TC_SMEM, s2>>>(x, N_NODES);
    cudaEventRecord(e2, s2);

    // branch B: CSR build
    scan1_kernel<<<N_SCAN_BLOCKS, SCAN_B>>>();
    scan2_kernel<<<1, 128>>>(N_SCAN_BLOCKS);
    scan3_kernel<<<(N_NODES + 255) / 256, 256>>>(E);
    int fillThreads = (E + 1) / 2;
    fill_kernel<<<(fillThreads + 255) / 256, 256>>>(eiw, E);

    // join, then gather
    cudaStreamWaitEvent(0, e2, 0);
    int gather_blocks = (N_NODES * 32 + 255) / 256;
    gather_kernel<<<gather_blocks, 256>>>(b, out);

    cudaEventDestroy(e1);
    cudaEventDestroy(e2);
    cudaStreamDestroy(s2);
}